// round 4
// baseline (speedup 1.0000x reference)
#include <cuda_runtime.h>
#include <math.h>

// Problem constants
#define NB    256   // batch
#define TP    32    // past length
#define TFUT  256   // future length
#define HH    100   // hidden H
#define HFF   275   // field hidden
#define HGG   75
#define HOO   75
#define K1    101   // H+1
#define K1P   104   // padded to /4
#define K2P   276   // 275 padded to /4

#define NTHR  288   // 9 warps
#define NCTA  128   // CTAs for encode/rollout (2 rows each)

// -------- device scratch (no allocations allowed) --------
__device__ __align__(16) float g_pW1[HFF * K1P];
__device__ __align__(16) float g_pW2[HFF * K2P];
__device__ __align__(16) float g_pW3[HH  * K2P];
__device__ float g_hB[NB * HH];
__device__ float g_gx[NB * 2];
__device__ float g_z0[NB * HH];

__device__ __forceinline__ float leaky1(float x) {
    const float SL = 1.0f / 5.5f;
    return x >= 0.f ? x : x * SL;
}
__device__ __forceinline__ float sigm1(float x) {
    return 1.f / (1.f + expf(-x));
}

// Dot of one weight row (length 4*NITER, padded with zeros) against a
// row-pair activation vector stored as float2[k] = (row0, row1).
// 8 independent accumulator chains for FMA-latency hiding.
template<int NITER, bool STREAM>
__device__ __forceinline__ float2 dot_row(const float* __restrict__ Wrow,
                                          const float2* __restrict__ xin,
                                          float bias) {
    const float4* wr = reinterpret_cast<const float4*>(Wrow);
    const float4* xr = reinterpret_cast<const float4*>(xin);
    float a00 = bias, a01 = 0.f, a02 = 0.f, a03 = 0.f;
    float a10 = bias, a11 = 0.f, a12 = 0.f, a13 = 0.f;
#pragma unroll 4
    for (int i = 0; i < NITER; i++) {
        float4 w = STREAM ? __ldcs(wr + i) : __ldg(wr + i);
        float4 p = xr[2 * i];       // (x[4i].r0, x[4i].r1, x[4i+1].r0, x[4i+1].r1)
        float4 q = xr[2 * i + 1];   // (x[4i+2].r0, ...)
        a00 = fmaf(w.x, p.x, a00);  a10 = fmaf(w.x, p.y, a10);
        a01 = fmaf(w.y, p.z, a01);  a11 = fmaf(w.y, p.w, a11);
        a02 = fmaf(w.z, q.x, a02);  a12 = fmaf(w.z, q.y, a12);
        a03 = fmaf(w.w, q.z, a03);  a13 = fmaf(w.w, q.w, a13);
    }
    return make_float2((a00 + a01) + (a02 + a03), (a10 + a11) + (a12 + a13));
}

// Field MLP: s_in (101 used, padded zeros at 101..103, pad slot 275) -> s_f.
// Ping-pong: L1: s_in->s_hid, L2: s_hid->s_in, L3: s_in->s_f.
// Caller must __syncthreads() after building s_in. Returns synced.
__device__ __forceinline__ void field_eval(int tid,
        float2* s_in, float2* s_hid, float2* s_f,
        const float* __restrict__ fb1, const float* __restrict__ fb2,
        const float* __restrict__ fb3) {
    if (tid < HFF) {
        float2 a = dot_row<K1P / 4, false>(g_pW1 + tid * K1P, s_in, __ldg(fb1 + tid));
        s_hid[tid] = make_float2(tanhf(a.x), tanhf(a.y));
    }
    __syncthreads();
    if (tid < HFF) {
        float2 a = dot_row<K2P / 4, true>(g_pW2 + tid * K2P, s_hid, __ldg(fb2 + tid));
        s_in[tid] = make_float2(tanhf(a.x), tanhf(a.y));
    }
    __syncthreads();
    if (tid < HH) {
        float2 a = dot_row<K2P / 4, false>(g_pW3 + tid * K2P, s_in, __ldg(fb3 + tid));
        s_f[tid] = make_float2(tanhf(a.x), tanhf(a.y));
    }
    __syncthreads();
}

// RK4 with NSUB=2 substeps: y (s_y) advanced from t0 to t1 (per-row times).
__device__ __forceinline__ void integrate2(int tid, float2 t0, float2 t1,
        float2* s_in, float2* s_hid, float2* s_y, float2* s_ks, float2* s_f,
        const float* __restrict__ fb1, const float* __restrict__ fb2,
        const float* __restrict__ fb3) {
    float2 dt = make_float2((t1.x - t0.x) * 0.5f, (t1.y - t0.y) * 0.5f);
#pragma unroll 1
    for (int sub = 0; sub < 2; sub++) {
        float2 t  = make_float2(t0.x + (float)sub * dt.x, t0.y + (float)sub * dt.y);
        float2 th = make_float2(t.x + 0.5f * dt.x, t.y + 0.5f * dt.y);
        float2 te = make_float2(t.x + dt.x, t.y + dt.y);

        // stage 1: x = [t, y]
        if (tid < HH)        s_in[1 + tid] = s_y[tid];
        else if (tid < 103)  s_in[1 + tid] = make_float2(0.f, 0.f);
        if (tid == 0)        s_in[0] = t;
        __syncthreads();
        field_eval(tid, s_in, s_hid, s_f, fb1, fb2, fb3);            // k1
        if (tid < HH) {
            float2 f = s_f[tid], y = s_y[tid];
            s_ks[tid] = f;
            s_in[1 + tid] = make_float2(fmaf(0.5f * dt.x, f.x, y.x),
                                        fmaf(0.5f * dt.y, f.y, y.y));
        } else if (tid < 103) s_in[1 + tid] = make_float2(0.f, 0.f);
        if (tid == 0) s_in[0] = th;
        __syncthreads();
        field_eval(tid, s_in, s_hid, s_f, fb1, fb2, fb3);            // k2
        if (tid < HH) {
            float2 f = s_f[tid], y = s_y[tid], k = s_ks[tid];
            s_ks[tid] = make_float2(k.x + 2.f * f.x, k.y + 2.f * f.y);
            s_in[1 + tid] = make_float2(fmaf(0.5f * dt.x, f.x, y.x),
                                        fmaf(0.5f * dt.y, f.y, y.y));
        } else if (tid < 103) s_in[1 + tid] = make_float2(0.f, 0.f);
        if (tid == 0) s_in[0] = th;
        __syncthreads();
        field_eval(tid, s_in, s_hid, s_f, fb1, fb2, fb3);            // k3
        if (tid < HH) {
            float2 f = s_f[tid], y = s_y[tid], k = s_ks[tid];
            s_ks[tid] = make_float2(k.x + 2.f * f.x, k.y + 2.f * f.y);
            s_in[1 + tid] = make_float2(fmaf(dt.x, f.x, y.x),
                                        fmaf(dt.y, f.y, y.y));
        } else if (tid < 103) s_in[1 + tid] = make_float2(0.f, 0.f);
        if (tid == 0) s_in[0] = te;
        __syncthreads();
        field_eval(tid, s_in, s_hid, s_f, fb1, fb2, fb3);            // k4
        if (tid < HH) {
            float2 f = s_f[tid], y = s_y[tid], k = s_ks[tid];
            s_y[tid] = make_float2(y.x + dt.x * (k.x + f.x) / 6.f,
                                   y.y + dt.y * (k.y + f.y) / 6.f);
        }
        __syncthreads();
    }
}

// -------- prep: pad field weights to /4 strides, zero padding --------
__global__ void prep_kernel(const float* __restrict__ fW1,
                            const float* __restrict__ fW2,
                            const float* __restrict__ fW3) {
    int i = blockIdx.x * blockDim.x + threadIdx.x;
    if (i < HFF * K1P) {
        int n = i / K1P, k = i % K1P;
        g_pW1[i] = (k < K1) ? fW1[n * K1 + k] : 0.f;
    }
    int j = i - HFF * K1P;
    if (j >= 0 && j < HFF * K2P) {
        int n = j / K2P, k = j % K2P;
        g_pW2[j] = (k < HFF) ? fW2[n * HFF + k] : 0.f;
    }
    int l = i - HFF * K1P - HFF * K2P;
    if (l >= 0 && l < HH * K2P) {
        int n = l / K2P, k = l % K2P;
        g_pW3[l] = (k < HFF) ? fW3[n * HFF + k] : 0.f;
    }
}

// -------- encode: 32 steps of (ODE integrate + GRU) per row-pair --------
__global__ void __launch_bounds__(NTHR) encode_kernel(
        const float* __restrict__ past, const float* __restrict__ h0,
        const float* __restrict__ fb1, const float* __restrict__ fb2,
        const float* __restrict__ fb3,
        const float* __restrict__ Wih, const float* __restrict__ Whh,
        const float* __restrict__ bih, const float* __restrict__ bhh) {
    __shared__ __align__(16) float2 s_in[K2P];
    __shared__ __align__(16) float2 s_hid[K2P];
    __shared__ __align__(16) float2 s_y[HH];
    __shared__ float2 s_ks[HH], s_f[HH];
    __shared__ float2 s_u[200], s_inn[HH], s_hn[HH];

    int tid = threadIdx.x;
    int r0 = blockIdx.x * 2, r1 = r0 + 1;

    if (tid == 0) { s_in[K2P - 1] = make_float2(0.f, 0.f); s_hid[K2P - 1] = make_float2(0.f, 0.f); }
    if (tid < HH) s_y[tid] = make_float2(h0[r0 * HH + tid], h0[r1 * HH + tid]);
    __syncthreads();

    float2 tprev = make_float2(0.f, 0.f);
    for (int step = 0; step < TP; step++) {
        float2 tcur = make_float2(past[(r0 * TP + step) * 2], past[(r1 * TP + step) * 2]);
        float2 t0 = (step == 0) ? make_float2(tcur.x - 1.f, tcur.y - 1.f) : tprev;
        integrate2(tid, t0, tcur, s_in, s_hid, s_y, s_ks, s_f, fb1, fb2, fb3);

        // GRU (D = 1): gi[j] = Wih[j]*x + bih[j]; gh[j] = Whh[j]·h + bhh[j]
        float2 x = make_float2(past[(r0 * TP + step) * 2 + 1], past[(r1 * TP + step) * 2 + 1]);
        for (int jj = tid; jj < 3 * HH; jj += NTHR) {
            float wi = __ldg(Wih + jj);
            float bi = __ldg(bih + jj);
            float2 gi = make_float2(fmaf(wi, x.x, bi), fmaf(wi, x.y, bi));
            float2 a = dot_row<HH / 4, false>(Whh + jj * HH, s_y, __ldg(bhh + jj));
            if (jj < 2 * HH) s_u[jj] = make_float2(gi.x + a.x, gi.y + a.y);
            else { s_inn[jj - 2 * HH] = gi; s_hn[jj - 2 * HH] = a; }
        }
        __syncthreads();
        if (tid < HH) {
            float2 u1 = s_u[tid], u2 = s_u[HH + tid];
            float2 gin = s_inn[tid], ghn = s_hn[tid], h = s_y[tid];
            float rx = sigm1(u1.x), ry = sigm1(u1.y);
            float zx = sigm1(u2.x), zy = sigm1(u2.y);
            float nx = tanhf(gin.x + rx * ghn.x), ny = tanhf(gin.y + ry * ghn.y);
            s_y[tid] = make_float2((1.f - zx) * nx + zx * h.x,
                                   (1.f - zy) * ny + zy * h.y);
        }
        __syncthreads();
        tprev = tcur;
    }
    if (tid < HH) {
        g_hB[r0 * HH + tid] = s_y[tid].x;
        g_hB[r1 * HH + tid] = s_y[tid].y;
    }
}

// -------- decoder head: gx = MLP(h) per row --------
__global__ void gx_kernel(const float* __restrict__ gW1, const float* __restrict__ gb1,
                          const float* __restrict__ gW2, const float* __restrict__ gb2,
                          const float* __restrict__ gW3, const float* __restrict__ gb3) {
    int b = blockIdx.x, tid = threadIdx.x;
    __shared__ float sh[HH], s1[HGG], s2[HGG];
    for (int k = tid; k < HH; k += blockDim.x) sh[k] = g_hB[b * HH + k];
    __syncthreads();
    if (tid < HGG) {
        float a = __ldg(gb1 + tid);
        const float* w = gW1 + tid * HH;
        for (int k = 0; k < HH; k++) a = fmaf(__ldg(w + k), sh[k], a);
        s1[tid] = leaky1(a);
    }
    __syncthreads();
    if (tid < HGG) {
        float a = __ldg(gb2 + tid);
        const float* w = gW2 + tid * HGG;
        for (int k = 0; k < HGG; k++) a = fmaf(__ldg(w + k), s1[k], a);
        s2[tid] = leaky1(a);
    }
    __syncthreads();
    if (tid < 2) {
        float a = __ldg(gb3 + tid);
        const float* w = gW3 + tid * HGG;
        for (int k = 0; k < HGG; k++) a = fmaf(__ldg(w + k), s2[k], a);
        g_gx[b * 2 + tid] = a;
    }
}

// -------- z0: reparameterization with the concat/reshape shuffle --------
__global__ void z0_kernel(const float* __restrict__ eps) {
    int b = blockIdx.x, h = threadIdx.x;
    // v[j] = j<256 ? gx[j][0] : |gx[j-256][1]| ; loc[b]=v[2b], scale[b]=v[2b+1]
    float loc, scale;
    if (b < NB / 2) {
        loc   = g_gx[(2 * b) * 2 + 0];
        scale = g_gx[(2 * b + 1) * 2 + 0];
    } else {
        int i = 2 * (b - NB / 2);
        loc   = fabsf(g_gx[i * 2 + 1]);
        scale = fabsf(g_gx[(i + 1) * 2 + 1]);
    }
    g_z0[b * HH + h] = loc + scale * eps[h * NB + b];
}

// -------- rollout: 255 integrations + output MLP per step --------
__device__ __forceinline__ void out_mlp(int tid, int s, int r0, int r1,
        float2* s_in, float2* s_hid, const float2* s_y,
        const float* __restrict__ oW1, const float* __restrict__ ob1,
        const float* __restrict__ oW2, const float* __restrict__ ob2,
        const float* __restrict__ oW3, const float* __restrict__ ob3,
        float* __restrict__ out) {
    if (tid < HOO) {
        float2 a = dot_row<HH / 4, false>(oW1 + tid * HH, s_y, __ldg(ob1 + tid));
        s_hid[tid] = make_float2(leaky1(a.x), leaky1(a.y));
    }
    __syncthreads();
    if (tid < HOO) {
        float a0 = __ldg(ob2 + tid), a1 = a0;
        const float* w = oW2 + tid * HOO;
        for (int k = 0; k < HOO; k++) {
            float wv = __ldg(w + k);
            float2 h = s_hid[k];
            a0 = fmaf(wv, h.x, a0); a1 = fmaf(wv, h.y, a1);
        }
        s_in[tid] = make_float2(leaky1(a0), leaky1(a1));
    }
    __syncthreads();
    if (tid == 0) {
        float a0 = __ldg(ob3), a1 = a0;
        for (int k = 0; k < HOO; k++) {
            float wv = __ldg(oW3 + k);
            float2 h = s_in[k];
            a0 = fmaf(wv, h.x, a0); a1 = fmaf(wv, h.y, a1);
        }
        out[r0 * TFUT + s] = a0;
        out[r1 * TFUT + s] = a1;
    }
    __syncthreads();
}

__global__ void __launch_bounds__(NTHR) rollout_kernel(
        const float* __restrict__ tf_,
        const float* __restrict__ fb1, const float* __restrict__ fb2,
        const float* __restrict__ fb3,
        const float* __restrict__ oW1, const float* __restrict__ ob1,
        const float* __restrict__ oW2, const float* __restrict__ ob2,
        const float* __restrict__ oW3, const float* __restrict__ ob3,
        float* __restrict__ out) {
    __shared__ __align__(16) float2 s_in[K2P];
    __shared__ __align__(16) float2 s_hid[K2P];
    __shared__ __align__(16) float2 s_y[HH];
    __shared__ float2 s_ks[HH], s_f[HH];

    int tid = threadIdx.x;
    int r0 = blockIdx.x * 2, r1 = r0 + 1;

    if (tid == 0) { s_in[K2P - 1] = make_float2(0.f, 0.f); s_hid[K2P - 1] = make_float2(0.f, 0.f); }
    if (tid < HH) s_y[tid] = make_float2(g_z0[r0 * HH + tid], g_z0[r1 * HH + tid]);
    __syncthreads();

    // t = 0 output (z0 itself)
    out_mlp(tid, 0, r0, r1, s_in, s_hid, s_y, oW1, ob1, oW2, ob2, oW3, ob3, out);

    float2 tprev = make_float2(tf_[r0 * TFUT], tf_[r1 * TFUT]);
    for (int s = 1; s < TFUT; s++) {
        float2 tcur = make_float2(tf_[r0 * TFUT + s], tf_[r1 * TFUT + s]);
        integrate2(tid, tprev, tcur, s_in, s_hid, s_y, s_ks, s_f, fb1, fb2, fb3);
        out_mlp(tid, s, r0, r1, s_in, s_hid, s_y, oW1, ob1, oW2, ob2, oW3, ob3, out);
        tprev = tcur;
    }
}

extern "C" void kernel_launch(void* const* d_in, const int* in_sizes, int n_in,
                              void* d_out, int out_size) {
    const float* past = (const float*)d_in[0];
    const float* h0   = (const float*)d_in[1];
    const float* t_fu = (const float*)d_in[2];
    const float* eps  = (const float*)d_in[3];
    const float* fW1  = (const float*)d_in[4];
    const float* fb1  = (const float*)d_in[5];
    const float* fW2  = (const float*)d_in[6];
    const float* fb2  = (const float*)d_in[7];
    const float* fW3  = (const float*)d_in[8];
    const float* fb3  = (const float*)d_in[9];
    const float* Wih  = (const float*)d_in[10];
    const float* Whh  = (const float*)d_in[11];
    const float* bih  = (const float*)d_in[12];
    const float* bhh  = (const float*)d_in[13];
    const float* gW1  = (const float*)d_in[14];
    const float* gb1  = (const float*)d_in[15];
    const float* gW2  = (const float*)d_in[16];
    const float* gb2  = (const float*)d_in[17];
    const float* gW3  = (const float*)d_in[18];
    const float* gb3  = (const float*)d_in[19];
    const float* oW1  = (const float*)d_in[20];
    const float* ob1  = (const float*)d_in[21];
    const float* oW2  = (const float*)d_in[22];
    const float* ob2  = (const float*)d_in[23];
    const float* oW3  = (const float*)d_in[24];
    const float* ob3  = (const float*)d_in[25];
    float* out = (float*)d_out;

    const int prep_total = HFF * K1P + HFF * K2P + HH * K2P;
    prep_kernel<<<(prep_total + 255) / 256, 256>>>(fW1, fW2, fW3);
    encode_kernel<<<NCTA, NTHR>>>(past, h0, fb1, fb2, fb3, Wih, Whh, bih, bhh);
    gx_kernel<<<NB, 96>>>(gW1, gb1, gW2, gb2, gW3, gb3);
    z0_kernel<<<NB, HH>>>(eps);
    rollout_kernel<<<NCTA, NTHR>>>(t_fu, fb1, fb2, fb3,
                                   oW1, ob1, oW2, ob2, oW3, ob3, out);
}